// round 9
// baseline (speedup 1.0000x reference)
#include <cuda_runtime.h>
#include <math.h>
#include <stdint.h>

#define CB 4
#define CL 2048
#define CC 1024
#define CNH 16
#define CHD 64
#define CK 16
#define CF4 256
#define CNC 128

// ---------------- scratch (device globals; no allocations allowed) ----------
__device__ float g_Q [CB*CL*CC];
__device__ float g_K [CB*CL*CC];
__device__ float g_V [CB*CL*CC];
__device__ float g_Y [CB*CL*CC];
__device__ float g_LR[CB*CNH*CL];

typedef unsigned long long u64t;

// ---------------- math helpers ----------------------------------------------
__device__ __forceinline__ float gelu_f(float x){
  float x2 = x*x;
  float t = tanhf(0.79788456f*x*(1.0f+0.044715f*x2));
  return 0.5f*x*(1.0f+t);
}
__device__ __forceinline__ float gelu_bwd_f(float x){
  float x2 = x*x;
  float t = tanhf(0.79788456f*x*(1.0f+0.044715f*x2));
  return 0.5f*x*((1.0f-t*t)*(0.79788456f + 0.1070322243f*x2)) + 0.5f*(1.0f+t);
}

// packed fp32x2 helpers (scalar blocks)
__device__ __forceinline__ u64t pk2(float x, float y){
  u64t r; asm("mov.b64 %0, {%1, %2};" : "=l"(r) : "f"(x), "f"(y)); return r;
}
__device__ __forceinline__ float2 upk(u64t v){
  float2 f; asm("mov.b64 {%0, %1}, %2;" : "=f"(f.x), "=f"(f.y) : "l"(v)); return f;
}
__device__ __forceinline__ u64t f2fma(u64t a, u64t b, u64t c){
  u64t d; asm("fma.rn.f32x2 %0, %1, %2, %3;" : "=l"(d) : "l"(a), "l"(b), "l"(c)); return d;
}

__device__ __forceinline__ uint32_t f2tf(float f){
  uint32_t u; asm("cvt.rna.tf32.f32 %0, %1;" : "=r"(u) : "f"(f)); return u;
}
__device__ __forceinline__ void sts_tf4(uint32_t* p, float4 v){
  uint4 u; u.x=f2tf(v.x); u.y=f2tf(v.y); u.z=f2tf(v.z); u.w=f2tf(v.w);
  *(uint4*)p = u;
}
__device__ __forceinline__ void mma_tf32(float* c, const uint32_t* a, const uint32_t* b){
  asm volatile("mma.sync.aligned.m16n8k8.row.col.f32.tf32.tf32.f32 "
    "{%0,%1,%2,%3}, {%4,%5,%6,%7}, {%8,%9}, {%0,%1,%2,%3};"
    : "+f"(c[0]),"+f"(c[1]),"+f"(c[2]),"+f"(c[3])
    : "r"(a[0]),"r"(a[1]),"r"(a[2]),"r"(a[3]), "r"(b[0]),"r"(b[1]));
}

// ---- 3xTF32 fragment helpers (fp32-accurate mma path) -----------------------
struct Frag4 { uint32_t h[4]; uint32_t l[4]; };
struct Frag2 { uint32_t h[2]; uint32_t l[2]; };

__device__ __forceinline__ void splitf(float f, uint32_t& h, uint32_t& l){
  h = f2tf(f);
  l = f2tf(f - __uint_as_float(h));
}
__device__ __forceinline__ Frag4 lda(const float* A, int m0, int k0, int AM, int AK, int g, int kq){
  Frag4 fr;
  splitf(A[(m0+g)*AM   + (k0+kq)*AK],   fr.h[0], fr.l[0]);
  splitf(A[(m0+g+8)*AM + (k0+kq)*AK],   fr.h[1], fr.l[1]);
  splitf(A[(m0+g)*AM   + (k0+kq+4)*AK], fr.h[2], fr.l[2]);
  splitf(A[(m0+g+8)*AM + (k0+kq+4)*AK], fr.h[3], fr.l[3]);
  return fr;
}
__device__ __forceinline__ Frag4 lda_s(const float* A, int m0, int k0, int AM, int AK, int g, int kq,
                                       const float* s){
  Frag4 fr;
  float s0 = s[k0+kq], s1 = s[k0+kq+4];
  splitf(A[(m0+g)*AM   + (k0+kq)*AK]*s0,   fr.h[0], fr.l[0]);
  splitf(A[(m0+g+8)*AM + (k0+kq)*AK]*s0,   fr.h[1], fr.l[1]);
  splitf(A[(m0+g)*AM   + (k0+kq+4)*AK]*s1, fr.h[2], fr.l[2]);
  splitf(A[(m0+g+8)*AM + (k0+kq+4)*AK]*s1, fr.h[3], fr.l[3]);
  return fr;
}
__device__ __forceinline__ Frag2 ldb(const float* B, int k0, int n0, int BK, int BN, int g, int kq){
  Frag2 fr;
  splitf(B[(k0+kq)*BK   + (n0+g)*BN], fr.h[0], fr.l[0]);
  splitf(B[(k0+kq+4)*BK + (n0+g)*BN], fr.h[1], fr.l[1]);
  return fr;
}
__device__ __forceinline__ Frag2 ldb_s(const float* B, int k0, int n0, int BK, int BN, int g, int kq,
                                       const float* s){
  Frag2 fr;
  splitf(B[(k0+kq)*BK   + (n0+g)*BN] * s[k0+kq],   fr.h[0], fr.l[0]);
  splitf(B[(k0+kq+4)*BK + (n0+g)*BN] * s[k0+kq+4], fr.h[1], fr.l[1]);
  return fr;
}
__device__ __forceinline__ void mma3(float* c, const Frag4& a, const Frag2& b){
  mma_tf32(c, a.h, b.h);
  mma_tf32(c, a.l, b.h);
  mma_tf32(c, a.h, b.l);
}

// ------------ tf32 tensor-core GEMM: C[M,N] = A[M,K] * B[N,K]^T -------------
__global__ __launch_bounds__(256) void gemm_tf32(
    const float* __restrict__ A, const float* __restrict__ B,
    float* __restrict__ C, int M, int N, int Kd)
{
  __shared__ uint32_t As[2][128*20];
  __shared__ uint32_t Bs[2][128*20];
  const int tid  = threadIdx.x;
  const int nt   = N >> 7;
  const int by   = blockIdx.x / nt;
  const int bx   = blockIdx.x % nt;
  const int wid  = tid >> 5;
  const int lane = tid & 31;
  const int wm   = (wid & 3) * 32;
  const int wn   = (wid >> 2) * 64;
  const int g    = lane >> 2;
  const int kq   = lane & 3;

  const int lrow = tid >> 1;
  const int lk   = (tid & 1) * 8;
  const float* Ag = A + (size_t)(by*128 + lrow)*Kd + lk;
  const float* Bg = B + (size_t)(bx*128 + lrow)*Kd + lk;
  const int sidx = lrow*20 + lk;

  float acc[2][8][4];
  #pragma unroll
  for (int i=0;i<2;i++)
    #pragma unroll
    for (int j=0;j<8;j++)
      #pragma unroll
      for (int k=0;k<4;k++) acc[i][j][k]=0.f;

  const int nk = Kd >> 4;
  float4 pa0 = *(const float4*)(Ag);
  float4 pa1 = *(const float4*)(Ag+4);
  float4 pb0 = *(const float4*)(Bg);
  float4 pb1 = *(const float4*)(Bg+4);
  sts_tf4(&As[0][sidx],   pa0);
  sts_tf4(&As[0][sidx+4], pa1);
  sts_tf4(&Bs[0][sidx],   pb0);
  sts_tf4(&Bs[0][sidx+4], pb1);

  for (int kt = 0; kt < nk; kt++){
    __syncthreads();
    if (kt+1 < nk){
      const float* Ap = Ag + (kt+1)*16;
      const float* Bp = Bg + (kt+1)*16;
      pa0 = *(const float4*)Ap; pa1 = *(const float4*)(Ap+4);
      pb0 = *(const float4*)Bp; pb1 = *(const float4*)(Bp+4);
    }
    const uint32_t* Ab = As[kt&1];
    const uint32_t* Bb = Bs[kt&1];
    #pragma unroll
    for (int k8 = 0; k8 < 2; k8++){
      const int ko = k8*8 + kq;
      uint32_t a[2][4], bf[8][2];
      #pragma unroll
      for (int fm=0; fm<2; fm++){
        int r = wm + fm*16 + g;
        a[fm][0] = Ab[r*20 + ko];
        a[fm][1] = Ab[(r+8)*20 + ko];
        a[fm][2] = Ab[r*20 + ko + 4];
        a[fm][3] = Ab[(r+8)*20 + ko + 4];
      }
      #pragma unroll
      for (int fn=0; fn<8; fn++){
        int r = wn + fn*8 + g;
        bf[fn][0] = Bb[r*20 + ko];
        bf[fn][1] = Bb[r*20 + ko + 4];
      }
      #pragma unroll
      for (int fm=0; fm<2; fm++)
        #pragma unroll
        for (int fn=0; fn<8; fn++)
          mma_tf32(acc[fm][fn], a[fm], bf[fn]);
    }
    if (kt+1 < nk){
      uint32_t* Aw = As[(kt+1)&1];
      uint32_t* Bw = Bs[(kt+1)&1];
      sts_tf4(&Aw[sidx],   pa0);
      sts_tf4(&Aw[sidx+4], pa1);
      sts_tf4(&Bw[sidx],   pb0);
      sts_tf4(&Bw[sidx+4], pb1);
    }
  }

  #pragma unroll
  for (int fm=0; fm<2; fm++){
    int r0 = by*128 + wm + fm*16 + g;
    #pragma unroll
    for (int fn=0; fn<8; fn++){
      int c = bx*128 + wn + fn*8 + kq*2;
      *(float2*)&C[(size_t)r0*N + c]     = make_float2(acc[fm][fn][0], acc[fm][fn][1]);
      *(float2*)&C[(size_t)(r0+8)*N + c] = make_float2(acc[fm][fn][2], acc[fm][fn][3]);
    }
  }
}

// ---------------- RoPE (interleaved pairs, pos = l mod 16) ------------------
__global__ __launch_bounds__(256) void rope_kernel(float* __restrict__ Q, float* __restrict__ Kt)
{
  const int PAIRS = CB*CL*CNH*(CHD/2);
  int i = blockIdx.x*blockDim.x + threadIdx.x;
  if (i >= 2*PAIRS) return;
  float* T = (i < PAIRS) ? Q : Kt;
  int j = (i < PAIRS) ? i : (i - PAIRS);
  int p = j & 31; j >>= 5;
  int h = j & 15; j >>= 4;
  int l = j & 2047;
  int b = j >> 11;
  float pos = (float)(l & 15);
  float ang = pos * exp2f(-(float)p * (13.287712379549449f/32.0f));
  float sn, cs;
  sincosf(ang, &sn, &cs);
  size_t base = ((size_t)(b*CL + l))*CC + h*CHD + 2*p;
  float2 x = *(float2*)&T[base];
  float2 y;
  y.x = x.x*cs - x.y*sn;
  y.y = x.y*cs + x.x*sn;
  *(float2*)&T[base] = y;
}

// ---------------- ttt_lr sigmoid dots: lr[b,h,l] ----------------------------
__global__ __launch_bounds__(256) void lr_kernel(
    const float* __restrict__ hs, const float* __restrict__ w,
    const float* __restrict__ bias, float* __restrict__ lr)
{
  __shared__ float row[CC];
  int bl = blockIdx.x;
  int tid = threadIdx.x;
  ((float4*)row)[tid] = ((const float4*)(hs + (size_t)bl*CC))[tid];
  __syncthreads();
  int h = tid >> 4, ln = tid & 15;
  float acc = 0.f;
  for (int c0 = ln*4; c0 < CC; c0 += 64){
    float4 r = *(const float4*)&row[c0];
    float4 wv = *(const float4*)&w[h*CC + c0];
    acc += r.x*wv.x + r.y*wv.y + r.z*wv.z + r.w*wv.w;
  }
  #pragma unroll
  for (int o=8;o;o>>=1) acc += __shfl_xor_sync(0xffffffffu, acc, o);
  if (ln == 0){
    int b = bl >> 11, l = bl & 2047;
    float v = acc + bias[h];
    lr[((size_t)(b*CNH + h))*CL + l] = 1.0f/(1.0f + expf(-v));
  }
}

// ---------------- scan kernel: one CTA per (b,h), 512 thr, tensor-core ------
// W1T[c][d]: stride 68  (W1T[c*68+d] = W1[d][c])
// W2T[d][f]: stride 260 (W2T[d*260+f] = W2[f][d])
#define OW1T 0        /* 256*68 = 17408 */
#define OW2T 17408    /* 64*260 = 16640 */
#define OB1  34048    /* 256 */
#define OB2  34304    /* 64  */
#define OLW  34368    /* 64  */
#define OLB  34432    /* 64  */
#define OXQ  34496    /* 16*68 */
#define OXK  35584
#define OXV  36672
#define OZ2  37760    /* 16*68 lower-K partial / final */
#define OZ2B 38848    /* 16*68 upper-K partial; reused as Attn2 raw half-1 */
#define OG2  39936    /* 16*68 */
#define OCC  41024    /* 16*17 (NEGATED tril coeffs) */
#define OTK  41296    /* 16 */
#define OLR  41312    /* 16 */
#define OCG  41328    /* 16 update coeffs */
#define OZ1  41344    /* 16*260 Z1 then X2bar */
#define OX2  45504    /* 16*260 */
#define OG1  49664    /* 16*260 */
#define SCAN_FLOATS 53824
#define SCAN_SMEM (SCAN_FLOATS*4)

__global__ __launch_bounds__(512) void scan_kernel(
  const float* __restrict__ Q, const float* __restrict__ Kx, const float* __restrict__ V,
  const float* __restrict__ LR, const float* __restrict__ lti,
  const float* __restrict__ lnw, const float* __restrict__ lnb,
  const float* __restrict__ W1g, const float* __restrict__ b1g,
  const float* __restrict__ W2g, const float* __restrict__ b2g,
  float* __restrict__ Y)
{
  extern __shared__ float sm[];
  const int t = threadIdx.x;
  const int bh = blockIdx.x;
  const int b = bh >> 4, h = bh & 15;
  float* sW1T = sm + OW1T;
  float* sW2T = sm + OW2T;
  float* sb1 = sm + OB1;
  float* sb2 = sm + OB2;
  float* sLW = sm + OLW;
  float* sLB = sm + OLB;
  float* sXQ = sm + OXQ;
  float* sXK = sm + OXK;
  float* sXV = sm + OXV;
  float* sZ2 = sm + OZ2;
  float* sZ2B= sm + OZ2B;
  float* sG2 = sm + OG2;
  float* sC  = sm + OCC;
  float* sTok= sm + OTK;
  float* sLr = sm + OLR;
  float* sCg = sm + OCG;
  float* sZ1 = sm + OZ1;
  float* sX2 = sm + OX2;
  float* sG1 = sm + OG1;

  // init state (transposed layouts)
  for (int idx = t; idx < 16384; idx += 512) {
    int d = idx >> 8, c = idx & 255;            // W1[d][c]
    sW1T[c*68+d] = W1g[h*16384 + idx];
  }
  for (int idx = t; idx < 16384; idx += 512) {
    int f = idx >> 6, d = idx & 63;             // W2[f][d]
    sW2T[d*260+f] = W2g[h*16384 + idx];
  }
  if (t < 256) sb1[t] = b1g[h*256+t];
  if (t < 64) { sb2[t] = b2g[h*64+t]; sLW[t] = lnw[h*64+t]; sLB[t] = lnb[h*64+t]; }
  if (t < 16) sTok[t] = fmaxf(1.0f/(float)(t+1) + lti[t], 0.0f);
  __syncthreads();

  const int tt  = t & 255;
  const int i16 = tt >> 4, l16 = tt & 15;   // 16x16 scalar mappings (t<256)
  const int half = t >> 8;                   // 0/1 for split 16x16 work
  const int w  = t >> 5;                     // warp 0..15
  const int lane = t & 31;
  const int g  = lane >> 2;
  const int kq = lane & 3;
  const int nw16 = w*16;                     // warp n-slice for N=256 (2 tiles)
  const int kgrp = w >> 3;                   // 0/1 K-half for N=64 stages
  const int nw8  = (w & 7)*8;                // warp n-slice for N=64

  for (int n = 0; n < CNC; n++) {
    const int l0 = n*16;
    // ===== stage 1: load tiles (split across halves) =====
    {
      size_t gbase = ((size_t)(b*CL + l0 + i16))*CC + h*CHD + l16*4;
      int sbase = i16*68 + l16*4;
      if (half == 0){
        *(float4*)&sXQ[sbase] = *(const float4*)&Q [gbase];
        *(float4*)&sXK[sbase] = *(const float4*)&Kx[gbase];
      } else {
        *(float4*)&sXV[sbase] = *(const float4*)&V [gbase];
      }
    }
    if (t < 16) {
      float lrv = LR[((size_t)bh)*CL + l0 + t] * (1.0f/64.0f);
      sLr[t] = lrv;
      sCg[t] = sTok[15] * lrv;
    }
    __syncthreads();

    // ===== stage 2: Z1 = XK@W1 + b1 (mma, 16 warps x 16 cols) ; Attn1 =====
    {
      float acc[2][4];
      #pragma unroll
      for (int a_=0;a_<2;a_++){ acc[a_][0]=0.f;acc[a_][1]=0.f;acc[a_][2]=0.f;acc[a_][3]=0.f; }
      #pragma unroll
      for (int k0=0;k0<64;k0+=8){
        Frag4 af = lda(sXK, 0, k0, 68, 1, g, kq);
        #pragma unroll
        for (int ntl=0;ntl<2;ntl++){
          Frag2 bf = ldb(sW1T, k0, nw16+ntl*8, 1, 68, g, kq);
          mma3(acc[ntl], af, bf);
        }
      }
      #pragma unroll
      for (int ntl=0;ntl<2;ntl++){
        int c0 = nw16+ntl*8 + kq*2;
        float bb0 = sb1[c0], bb1 = sb1[c0+1];
        float z;
        z = acc[ntl][0]+bb0; sZ1[g*260+c0]       = z; sX2[g*260+c0]       = gelu_f(z);
        z = acc[ntl][1]+bb1; sZ1[g*260+c0+1]     = z; sX2[g*260+c0+1]     = gelu_f(z);
        z = acc[ntl][2]+bb0; sZ1[(g+8)*260+c0]   = z; sX2[(g+8)*260+c0]   = gelu_f(z);
        z = acc[ntl][3]+bb1; sZ1[(g+8)*260+c0+1] = z; sX2[(g+8)*260+c0+1] = gelu_f(z);
      }
    }
    if (half == 0) { // Attn1 (NEGATED): sC[i][j] = -tok_i*lr_j*(xq_i.xk_j+1), j<=i
      float c = 0.0f;
      if (l16 <= i16) {
        u64t acc = 0ULL;
        #pragma unroll
        for (int d0=0; d0<64; d0+=4) {
          float4 xq = *(const float4*)&sXQ[i16*68+d0];
          float4 xk = *(const float4*)&sXK[l16*68+d0];
          acc = f2fma(pk2(xq.x,xq.y), pk2(xk.x,xk.y), acc);
          acc = f2fma(pk2(xq.z,xq.w), pk2(xk.z,xk.w), acc);
        }
        float2 p = upk(acc);
        c = -sTok[i16]*sLr[l16]*(p.x + p.y + 1.0f);
      }
      sC[i16*17+l16] = c;
    }
    __syncthreads();

    // ===== stage 3: Z2 = X2@W2 + b2 (mma, K split across warp groups) =====
    {
      float acc[4] = {0.f,0.f,0.f,0.f};
      const int kbase = kgrp*128;
      #pragma unroll 4
      for (int kk=0;kk<128;kk+=8){
        int k0 = kbase + kk;
        Frag4 af = lda(sX2, 0, k0, 260, 1, g, kq);
        Frag2 bf = ldb(sW2T, k0, nw8, 1, 260, g, kq);
        mma3(acc, af, bf);
      }
      int c0 = nw8 + kq*2;
      if (kgrp == 0){
        sZ2[g*68+c0]       = acc[0] + sb2[c0];
        sZ2[g*68+c0+1]     = acc[1] + sb2[c0+1];
        sZ2[(g+8)*68+c0]   = acc[2] + sb2[c0];
        sZ2[(g+8)*68+c0+1] = acc[3] + sb2[c0+1];
      } else {
        sZ2B[g*68+c0]       = acc[0];
        sZ2B[g*68+c0+1]     = acc[1];
        sZ2B[(g+8)*68+c0]   = acc[2];
        sZ2B[(g+8)*68+c0+1] = acc[3];
      }
    }
    __syncthreads();

    // ===== stage 4: gZ2 = ln_fused_l2_bwd(Z2, XV-XK) (scalar, t<256) =====
    if (half == 0) {
      int base = i16*68 + l16*4;
      float4 xa = *(const float4*)&sZ2[base];
      float4 xb = *(const float4*)&sZ2B[base];
      float4 x;
      x.x = xa.x+xb.x; x.y = xa.y+xb.y; x.z = xa.z+xb.z; x.w = xa.w+xb.w;
      float s  = x.x+x.y+x.z+x.w;
      float ss = x.x*x.x + x.y*x.y + x.z*x.z + x.w*x.w;
      #pragma unroll
      for (int o=8;o;o>>=1){ s += __shfl_xor_sync(0xffffffffu, s, o); ss += __shfl_xor_sync(0xffffffffu, ss, o); }
      float mu = s*(1.0f/64.0f);
      float var = ss*(1.0f/64.0f) - mu*mu;
      float rstd = rsqrtf(var + 1e-6f);
      float4 xh;
      xh.x=(x.x-mu)*rstd; xh.y=(x.y-mu)*rstd; xh.z=(x.z-mu)*rstd; xh.w=(x.w-mu)*rstd;
      float4 gw = *(const float4*)&sLW[l16*4];
      float4 bb = *(const float4*)&sLB[l16*4];
      float4 xv = *(const float4*)&sXV[base];
      float4 xk = *(const float4*)&sXK[base];
      float4 go;
      go.x = (gw.x*xh.x + bb.x - (xv.x - xk.x))*gw.x;
      go.y = (gw.y*xh.y + bb.y - (xv.y - xk.y))*gw.y;
      go.z = (gw.z*xh.z + bb.z - (xv.z - xk.z))*gw.z;
      go.w = (gw.w*xh.w + bb.w - (xv.w - xk.w))*gw.w;
      float sg  = go.x+go.y+go.z+go.w;
      float sgx = go.x*xh.x + go.y*xh.y + go.z*xh.z + go.w*xh.w;
      #pragma unroll
      for (int o=8;o;o>>=1){ sg += __shfl_xor_sync(0xffffffffu, sg, o); sgx += __shfl_xor_sync(0xffffffffu, sgx, o); }
      float k1 = rstd*(1.0f/64.0f);
      float4 o4;
      o4.x = (64.0f*go.x - sg - xh.x*sgx)*k1;
      o4.y = (64.0f*go.y - sg - xh.y*sgx)*k1;
      o4.z = (64.0f*go.z - sg - xh.z*sgx)*k1;
      o4.w = (64.0f*go.w - sg - xh.w*sgx)*k1;
      *(float4*)&sG2[base] = o4;
    }
    __syncthreads();

    // ===== stage 5: gZ1 = (gZ2 @ W2^T) * gelu'(Z1) (mma) =====
    {
      float acc[2][4];
      #pragma unroll
      for (int a_=0;a_<2;a_++){ acc[a_][0]=0.f;acc[a_][1]=0.f;acc[a_][2]=0.f;acc[a_][3]=0.f; }
      #pragma unroll
      for (int k0=0;k0<64;k0+=8){
        Frag4 af = lda(sG2, 0, k0, 68, 1, g, kq);
        #pragma unroll
        for (int ntl=0;ntl<2;ntl++){
          Frag2 bf = ldb(sW2T, k0, nw16+ntl*8, 260, 1, g, kq);
          mma3(acc[ntl], af, bf);
        }
      }
      #pragma unroll
      for (int ntl=0;ntl<2;ntl++){
        int c0 = nw16+ntl*8 + kq*2;
        sG1[g*260+c0]       = acc[ntl][0]*gelu_bwd_f(sZ1[g*260+c0]);
        sG1[g*260+c0+1]     = acc[ntl][1]*gelu_bwd_f(sZ1[g*260+c0+1]);
        sG1[(g+8)*260+c0]   = acc[ntl][2]*gelu_bwd_f(sZ1[(g+8)*260+c0]);
        sG1[(g+8)*260+c0+1] = acc[ntl][3]*gelu_bwd_f(sZ1[(g+8)*260+c0+1]);
      }
    }
    __syncthreads();

    // ===== stage 6: Z1bar = XQ@W1 + (-C)@gZ1 + b1 ; X2bar = gelu -> sZ1 ====
    {
      float acc[2][4];
      #pragma unroll
      for (int a_=0;a_<2;a_++){ acc[a_][0]=0.f;acc[a_][1]=0.f;acc[a_][2]=0.f;acc[a_][3]=0.f; }
      #pragma unroll
      for (int k0=0;k0<64;k0+=8){
        Frag4 af = lda(sXQ, 0, k0, 68, 1, g, kq);
        #pragma unroll
        for (int ntl=0;ntl<2;ntl++){
          Frag2 bf = ldb(sW1T, k0, nw16+ntl*8, 1, 68, g, kq);
          mma3(acc[ntl], af, bf);
        }
      }
      #pragma unroll
      for (int k0=0;k0<16;k0+=8){
        Frag4 af = lda(sC, 0, k0, 17, 1, g, kq);
        #pragma unroll
        for (int ntl=0;ntl<2;ntl++){
          Frag2 bf = ldb(sG1, k0, nw16+ntl*8, 260, 1, g, kq);
          mma3(acc[ntl], af, bf);
        }
      }
      #pragma unroll
      for (int ntl=0;ntl<2;ntl++){
        int c0 = nw16+ntl*8 + kq*2;
        float bb0 = sb1[c0], bb1 = sb1[c0+1];
        sZ1[g*260+c0]       = gelu_f(acc[ntl][0]+bb0);
        sZ1[g*260+c0+1]     = gelu_f(acc[ntl][1]+bb1);
        sZ1[(g+8)*260+c0]   = gelu_f(acc[ntl][2]+bb0);
        sZ1[(g+8)*260+c0+1] = gelu_f(acc[ntl][3]+bb1);
      }
    }
    __syncthreads();

    // ===== stage 7: Attn2 raw dots, split K across halves =====
    {
      if (l16 <= i16) {
        u64t acc = 0ULL;
        const int f0b = half*128;
        #pragma unroll 8
        for (int f0=0; f0<128; f0+=4) {
          float4 xb = *(const float4*)&sZ1[i16*260+f0b+f0];
          float4 x2 = *(const float4*)&sX2[l16*260+f0b+f0];
          acc = f2fma(pk2(xb.x,xb.y), pk2(x2.x,x2.y), acc);
          acc = f2fma(pk2(xb.z,xb.w), pk2(x2.z,x2.w), acc);
        }
        float2 p = upk(acc);
        float raw = p.x + p.y;
        if (half == 0) sC[i16*17+l16] = raw;
        else           sZ2B[i16*17+l16] = raw;
      }
    }
    __syncthreads();
    // combine halves, negate+scale
    if (half == 0) {
      float c = 0.0f;
      if (l16 <= i16)
        c = -sTok[i16]*sLr[l16]*(sC[i16*17+l16] + sZ2B[i16*17+l16] + 1.0f);
      sC[i16*17+l16] = c;
    }
    __syncthreads();

    // ===== stage 8: Z2bar = X2bar@W2 + (-C)@gZ2 + b2 (mma, K split) =====
    {
      float acc[4] = {0.f,0.f,0.f,0.f};
      const int kbase = kgrp*128;
      #pragma unroll 4
      for (int kk=0;kk<128;kk+=8){
        int k0 = kbase + kk;
        Frag4 af = lda(sZ1, 0, k0, 260, 1, g, kq);
        Frag2 bf = ldb(sW2T, k0, nw8, 1, 260, g, kq);
        mma3(acc, af, bf);
      }
      int c0 = nw8 + kq*2;
      if (kgrp == 0){
        #pragma unroll
        for (int k0=0;k0<16;k0+=8){
          Frag4 af = lda(sC, 0, k0, 17, 1, g, kq);
          Frag2 bf = ldb(sG2, k0, nw8, 68, 1, g, kq);
          mma3(acc, af, bf);
        }
        sZ2[g*68+c0]       = acc[0] + sb2[c0];
        sZ2[g*68+c0+1]     = acc[1] + sb2[c0+1];
        sZ2[(g+8)*68+c0]   = acc[2] + sb2[c0];
        sZ2[(g+8)*68+c0+1] = acc[3] + sb2[c0+1];
      } else {
        sZ2B[g*68+c0]       = acc[0];
        sZ2B[g*68+c0+1]     = acc[1];
        sZ2B[(g+8)*68+c0]   = acc[2];
        sZ2B[(g+8)*68+c0+1] = acc[3];
      }
    }
    __syncthreads();

    // ===== stage 9: output LN (t<256) + W/b updates (all threads) =====
    if (half == 0) { // Y = XQ + ln_fwd(Z2bar)
      int base = i16*68 + l16*4;
      float4 xa = *(const float4*)&sZ2[base];
      float4 xc = *(const float4*)&sZ2B[base];
      float4 x;
      x.x = xa.x+xc.x; x.y = xa.y+xc.y; x.z = xa.z+xc.z; x.w = xa.w+xc.w;
      float s  = x.x+x.y+x.z+x.w;
      float ss = x.x*x.x + x.y*x.y + x.z*x.z + x.w*x.w;
      #pragma unroll
      for (int o=8;o;o>>=1){ s += __shfl_xor_sync(0xffffffffu, s, o); ss += __shfl_xor_sync(0xffffffffu, ss, o); }
      float mu = s*(1.0f/64.0f);
      float var = ss*(1.0f/64.0f) - mu*mu;
      float rstd = rsqrtf(var + 1e-6f);
      float4 gw = *(const float4*)&sLW[l16*4];
      float4 bb = *(const float4*)&sLB[l16*4];
      float4 xq = *(const float4*)&sXQ[base];
      float4 o4;
      o4.x = gw.x*(x.x-mu)*rstd + bb.x + xq.x;
      o4.y = gw.y*(x.y-mu)*rstd + bb.y + xq.y;
      o4.z = gw.z*(x.z-mu)*rstd + bb.z + xq.z;
      o4.w = gw.w*(x.w-mu)*rstd + bb.w + xq.w;
      size_t gbase = ((size_t)(b*CL + l0 + i16))*CC + h*CHD + l16*4;
      *(float4*)&Y[gbase] = o4;
    }
    // W1T[c][d] -= sum_j XK[j][d] * (cg_j * gZ1[j][c])   (16 warps x 16 cols)
    {
      #pragma unroll
      for (int mt=0; mt<4; mt++){
        float acc[2][4];
        #pragma unroll
        for (int a_=0;a_<2;a_++){ acc[a_][0]=0.f;acc[a_][1]=0.f;acc[a_][2]=0.f;acc[a_][3]=0.f; }
        #pragma unroll
        for (int k0=0;k0<16;k0+=8){
          Frag4 af = lda(sXK, mt*16, k0, 1, 68, g, kq);
          #pragma unroll
          for (int ntl=0;ntl<2;ntl++){
            Frag2 bf = ldb_s(sG1, k0, nw16+ntl*8, 260, 1, g, kq, sCg);
            mma3(acc[ntl], af, bf);
          }
        }
        int d0 = mt*16 + g;
        #pragma unroll
        for (int ntl=0;ntl<2;ntl++){
          int c0 = nw16+ntl*8 + kq*2;
          sW1T[c0*68+d0]       -= acc[ntl][0];
          sW1T[(c0+1)*68+d0]   -= acc[ntl][1];
          sW1T[c0*68+d0+8]     -= acc[ntl][2];
          sW1T[(c0+1)*68+d0+8] -= acc[ntl][3];
        }
      }
    }
    // W2T[d][f] -= sum_j (cg_j * gZ2[j][d]) * X2[j][f]   (16 warps x 16 cols)
    {
      #pragma unroll
      for (int mt=0; mt<4; mt++){
        float acc[2][4];
        #pragma unroll
        for (int a_=0;a_<2;a_++){ acc[a_][0]=0.f;acc[a_][1]=0.f;acc[a_][2]=0.f;acc[a_][3]=0.f; }
        #pragma unroll
        for (int k0=0;k0<16;k0+=8){
          Frag4 af = lda_s(sG2, mt*16, k0, 1, 68, g, kq, sCg);
          #pragma unroll
          for (int ntl=0;ntl<2;ntl++){
            Frag2 bf = ldb(sX2, k0, nw16+ntl*8, 260, 1, g, kq);
            mma3(acc[ntl], af, bf);
          }
        }
        int d0 = mt*16 + g;
        #pragma unroll
        for (int ntl=0;ntl<2;ntl++){
          int f0 = nw16+ntl*8 + kq*2;
          sW2T[d0*260+f0]       -= acc[ntl][0];
          sW2T[d0*260+f0+1]     -= acc[ntl][1];
          sW2T[(d0+8)*260+f0]   -= acc[ntl][2];
          sW2T[(d0+8)*260+f0+1] -= acc[ntl][3];
        }
      }
    }
    // bias updates (scalar)
    if (half == 0) {
      float s1 = 0.f;
      #pragma unroll
      for (int j=0;j<16;j++) s1 += sCg[j]*sG1[j*260+tt];
      sb1[tt] -= s1;
      if (tt < 64){
        float s2 = 0.f;
        #pragma unroll
        for (int j=0;j<16;j++) s2 += sCg[j]*sG2[j*68+tt];
        sb2[tt] -= s2;
      }
    }
    __syncthreads();
  }
}

// ---------------- post layernorm over C=1024 --------------------------------
__global__ __launch_bounds__(256) void postln_kernel(
    const float* __restrict__ X, const float* __restrict__ g,
    const float* __restrict__ b, float* __restrict__ O)
{
  __shared__ float rs[8], rss[8], stats[2];
  int row = blockIdx.x, t = threadIdx.x;
  float4 x = ((const float4*)(X + (size_t)row*CC))[t];
  float s  = x.x+x.y+x.z+x.w;
  float ss = x.x*x.x + x.y*x.y + x.z*x.z + x.w*x.w;
  #pragma unroll
  for (int o=16;o;o>>=1){ s += __shfl_xor_sync(0xffffffffu, s, o); ss += __shfl_xor_sync(0xffffffffu, ss, o); }
  if ((t & 31) == 0){ rs[t>>5] = s; rss[t>>5] = ss; }
  __syncthreads();
  if (t == 0){
    float a=0.f, c=0.f;
    #pragma unroll
    for (int w=0;w<8;w++){ a += rs[w]; c += rss[w]; }
    stats[0] = a*(1.0f/1024.0f);
    stats[1] = c*(1.0f/1024.0f);
  }
  __syncthreads();
  float mu = stats[0];
  float var = stats[1] - mu*mu;
  float rstd = rsqrtf(var + 1e-6f);
  float4 gv = ((const float4*)g)[t];
  float4 bv = ((const float4*)b)[t];
  float4 o4;
  o4.x = gv.x*(x.x-mu)*rstd + bv.x;
  o4.y = gv.y*(x.y-mu)*rstd + bv.y;
  o4.z = gv.z*(x.z-mu)*rstd + bv.z;
  o4.w = gv.w*(x.w-mu)*rstd + bv.w;
  ((float4*)(O + (size_t)row*CC))[t] = o4;
}

// ---------------- launch -----------------------------------------------------
extern "C" void kernel_launch(void* const* d_in, const int* in_sizes, int n_in,
                              void* d_out, int out_size)
{
  const float* hs  = (const float*)d_in[0];
  const float* wq  = (const float*)d_in[1];
  const float* wk  = (const float*)d_in[2];
  const float* wv  = (const float*)d_in[3];
  const float* wo  = (const float*)d_in[4];
  const float* lti = (const float*)d_in[5];
  const float* lrw = (const float*)d_in[6];
  const float* lrb = (const float*)d_in[7];
  const float* tnw = (const float*)d_in[8];
  const float* tnb = (const float*)d_in[9];
  const float* pnw = (const float*)d_in[10];
  const float* pnb = (const float*)d_in[11];
  const float* W1  = (const float*)d_in[12];
  const float* b1  = (const float*)d_in[13];
  const float* W2  = (const float*)d_in[14];
  const float* b2  = (const float*)d_in[15];
  float* out = (float*)d_out;

  float *pQ, *pK, *pV, *pY, *pLR;
  cudaGetSymbolAddress((void**)&pQ,  g_Q);
  cudaGetSymbolAddress((void**)&pK,  g_K);
  cudaGetSymbolAddress((void**)&pV,  g_V);
  cudaGetSymbolAddress((void**)&pY,  g_Y);
  cudaGetSymbolAddress((void**)&pLR, g_LR);

  cudaFuncSetAttribute(scan_kernel, cudaFuncAttributeMaxDynamicSharedMemorySize, SCAN_SMEM);

  const int M = CB*CL;  // 8192
  const int GG = (M/128)*(CC/128);  // 512
  gemm_tf32<<<GG, 256>>>(hs, wq, pQ, M, CC, CC);
  gemm_tf32<<<GG, 256>>>(hs, wk, pK, M, CC, CC);
  gemm_tf32<<<GG, 256>>>(hs, wv, pV, M, CC, CC);
  rope_kernel<<<(2*CB*CL*CNH*(CHD/2))/256, 256>>>(pQ, pK);
  lr_kernel<<<CB*CL, 256>>>(hs, lrw, lrb, pLR);
  scan_kernel<<<CB*CNH, 512, SCAN_SMEM>>>(pQ, pK, pV, pLR, lti, tnw, tnb,
                                          W1, b1, W2, b2, pY);
  postln_kernel<<<CB*CL, 256>>>(pY, pnw, pnb, pQ);
  gemm_tf32<<<GG, 256>>>(pQ, wo, out, M, CC, CC);
}

// round 10
// speedup vs baseline: 1.2509x; 1.2509x over previous
#include <cuda_runtime.h>
#include <math.h>
#include <stdint.h>

#define CB 4
#define CL 2048
#define CC 1024
#define CNH 16
#define CHD 64
#define CK 16
#define CF4 256
#define CNC 128

// ---------------- scratch (device globals; no allocations allowed) ----------
__device__ float g_Q [CB*CL*CC];
__device__ float g_K [CB*CL*CC];
__device__ float g_V [CB*CL*CC];
__device__ float g_Y [CB*CL*CC];
__device__ float g_LR[CB*CNH*CL];

typedef unsigned long long u64t;

// ---------------- math helpers ----------------------------------------------
__device__ __forceinline__ float gelu_f(float x){
  float x2 = x*x;
  float t = tanhf(0.79788456f*x*(1.0f+0.044715f*x2));
  return 0.5f*x*(1.0f+t);
}
__device__ __forceinline__ float gelu_bwd_f(float x){
  float x2 = x*x;
  float t = tanhf(0.79788456f*x*(1.0f+0.044715f*x2));
  return 0.5f*x*((1.0f-t*t)*(0.79788456f + 0.1070322243f*x2)) + 0.5f*(1.0f+t);
}

// packed fp32x2 helpers (scalar blocks)
__device__ __forceinline__ u64t pk2(float x, float y){
  u64t r; asm("mov.b64 %0, {%1, %2};" : "=l"(r) : "f"(x), "f"(y)); return r;
}
__device__ __forceinline__ float2 upk(u64t v){
  float2 f; asm("mov.b64 {%0, %1}, %2;" : "=f"(f.x), "=f"(f.y) : "l"(v)); return f;
}
__device__ __forceinline__ u64t f2fma(u64t a, u64t b, u64t c){
  u64t d; asm("fma.rn.f32x2 %0, %1, %2, %3;" : "=l"(d) : "l"(a), "l"(b), "l"(c)); return d;
}

__device__ __forceinline__ uint32_t f2tf(float f){
  uint32_t u; asm("cvt.rna.tf32.f32 %0, %1;" : "=r"(u) : "f"(f)); return u;
}
__device__ __forceinline__ void sts_tf4(uint32_t* p, float4 v){
  uint4 u; u.x=f2tf(v.x); u.y=f2tf(v.y); u.z=f2tf(v.z); u.w=f2tf(v.w);
  *(uint4*)p = u;
}
__device__ __forceinline__ void mma_tf32(float* c, const uint32_t* a, const uint32_t* b){
  asm volatile("mma.sync.aligned.m16n8k8.row.col.f32.tf32.tf32.f32 "
    "{%0,%1,%2,%3}, {%4,%5,%6,%7}, {%8,%9}, {%0,%1,%2,%3};"
    : "+f"(c[0]),"+f"(c[1]),"+f"(c[2]),"+f"(c[3])
    : "r"(a[0]),"r"(a[1]),"r"(a[2]),"r"(a[3]), "r"(b[0]),"r"(b[1]));
}

// ---- split-BF16 (3-term) fragment helpers for the scan ---------------------
// x = hi(bf16) + lo(bf16) + O(2^-16); product sum via hh + lh + hl.
__device__ __forceinline__ uint32_t bfpack(float lo, float hi){
  uint32_t r; asm("cvt.rn.bf16x2.f32 %0, %1, %2;" : "=r"(r) : "f"(hi), "f"(lo)); return r;
}
__device__ __forceinline__ void bfsplit2(float x, float y, uint32_t& h, uint32_t& l){
  h = bfpack(x, y);
  float hx = __uint_as_float(h << 16);
  float hy = __uint_as_float(h & 0xffff0000u);
  l = bfpack(x - hx, y - hy);
}
struct FragAb { uint32_t h[4]; uint32_t l[4]; };
struct FragBb { uint32_t h[2]; uint32_t l[2]; };

__device__ __forceinline__ FragAb lda_b(const float* A, int m0, int k0, int AM, int AK, int g, int kq){
  FragAb fr;
  int r0 = (m0+g)*AM, r1 = (m0+g+8)*AM;
  int c0 = (k0+2*kq)*AK, c1 = c0+AK;
  int c2 = (k0+2*kq+8)*AK, c3 = c2+AK;
  bfsplit2(A[r0+c0], A[r0+c1], fr.h[0], fr.l[0]);
  bfsplit2(A[r1+c0], A[r1+c1], fr.h[1], fr.l[1]);
  bfsplit2(A[r0+c2], A[r0+c3], fr.h[2], fr.l[2]);
  bfsplit2(A[r1+c2], A[r1+c3], fr.h[3], fr.l[3]);
  return fr;
}
__device__ __forceinline__ FragAb lda_bs(const float* A, int m0, int k0, int AM, int AK, int g, int kq,
                                         const float* s){
  FragAb fr;
  int r0 = (m0+g)*AM, r1 = (m0+g+8)*AM;
  int c0 = (k0+2*kq)*AK, c1 = c0+AK;
  int c2 = (k0+2*kq+8)*AK, c3 = c2+AK;
  float s0 = s[k0+2*kq], s1 = s[k0+2*kq+1], s2 = s[k0+2*kq+8], s3 = s[k0+2*kq+9];
  bfsplit2(A[r0+c0]*s0, A[r0+c1]*s1, fr.h[0], fr.l[0]);
  bfsplit2(A[r1+c0]*s0, A[r1+c1]*s1, fr.h[1], fr.l[1]);
  bfsplit2(A[r0+c2]*s2, A[r0+c3]*s3, fr.h[2], fr.l[2]);
  bfsplit2(A[r1+c2]*s2, A[r1+c3]*s3, fr.h[3], fr.l[3]);
  return fr;
}
__device__ __forceinline__ FragBb ldb_b(const float* B, int k0, int n0, int BK, int BN, int g, int kq){
  FragBb fr;
  int nn = (n0+g)*BN;
  int k0i = (k0+2*kq)*BK;
  int k1i = (k0+2*kq+8)*BK;
  bfsplit2(B[k0i+nn], B[k0i+BK+nn], fr.h[0], fr.l[0]);
  bfsplit2(B[k1i+nn], B[k1i+BK+nn], fr.h[1], fr.l[1]);
  return fr;
}
__device__ __forceinline__ FragBb ldb_bs(const float* B, int k0, int n0, int BK, int BN, int g, int kq,
                                         const float* s){
  FragBb fr;
  int nn = (n0+g)*BN;
  int k0i = (k0+2*kq)*BK;
  int k1i = (k0+2*kq+8)*BK;
  float s0 = s[k0+2*kq], s1 = s[k0+2*kq+1], s2 = s[k0+2*kq+8], s3 = s[k0+2*kq+9];
  bfsplit2(B[k0i+nn]*s0, B[k0i+BK+nn]*s1, fr.h[0], fr.l[0]);
  bfsplit2(B[k1i+nn]*s2, B[k1i+BK+nn]*s3, fr.h[1], fr.l[1]);
  return fr;
}
__device__ __forceinline__ void mma_b16(float* c, const uint32_t* a, const uint32_t* b){
  asm volatile("mma.sync.aligned.m16n8k16.row.col.f32.bf16.bf16.f32 "
    "{%0,%1,%2,%3}, {%4,%5,%6,%7}, {%8,%9}, {%0,%1,%2,%3};"
    : "+f"(c[0]),"+f"(c[1]),"+f"(c[2]),"+f"(c[3])
    : "r"(a[0]),"r"(a[1]),"r"(a[2]),"r"(a[3]), "r"(b[0]),"r"(b[1]));
}
__device__ __forceinline__ void mma3b(float* c, const FragAb& a, const FragBb& b){
  mma_b16(c, a.h, b.h);
  mma_b16(c, a.l, b.h);
  mma_b16(c, a.h, b.l);
}

// ------------ tf32 tensor-core GEMM: C[M,N] = A[M,K] * B[N,K]^T -------------
__global__ __launch_bounds__(256) void gemm_tf32(
    const float* __restrict__ A, const float* __restrict__ B,
    float* __restrict__ C, int M, int N, int Kd)
{
  __shared__ uint32_t As[2][128*20];
  __shared__ uint32_t Bs[2][128*20];
  const int tid  = threadIdx.x;
  const int nt   = N >> 7;
  const int by   = blockIdx.x / nt;
  const int bx   = blockIdx.x % nt;
  const int wid  = tid >> 5;
  const int lane = tid & 31;
  const int wm   = (wid & 3) * 32;
  const int wn   = (wid >> 2) * 64;
  const int g    = lane >> 2;
  const int kq   = lane & 3;

  const int lrow = tid >> 1;
  const int lk   = (tid & 1) * 8;
  const float* Ag = A + (size_t)(by*128 + lrow)*Kd + lk;
  const float* Bg = B + (size_t)(bx*128 + lrow)*Kd + lk;
  const int sidx = lrow*20 + lk;

  float acc[2][8][4];
  #pragma unroll
  for (int i=0;i<2;i++)
    #pragma unroll
    for (int j=0;j<8;j++)
      #pragma unroll
      for (int k=0;k<4;k++) acc[i][j][k]=0.f;

  const int nk = Kd >> 4;
  float4 pa0 = *(const float4*)(Ag);
  float4 pa1 = *(const float4*)(Ag+4);
  float4 pb0 = *(const float4*)(Bg);
  float4 pb1 = *(const float4*)(Bg+4);
  sts_tf4(&As[0][sidx],   pa0);
  sts_tf4(&As[0][sidx+4], pa1);
  sts_tf4(&Bs[0][sidx],   pb0);
  sts_tf4(&Bs[0][sidx+4], pb1);

  for (int kt = 0; kt < nk; kt++){
    __syncthreads();
    if (kt+1 < nk){
      const float* Ap = Ag + (kt+1)*16;
      const float* Bp = Bg + (kt+1)*16;
      pa0 = *(const float4*)Ap; pa1 = *(const float4*)(Ap+4);
      pb0 = *(const float4*)Bp; pb1 = *(const float4*)(Bp+4);
    }
    const uint32_t* Ab = As[kt&1];
    const uint32_t* Bb = Bs[kt&1];
    #pragma unroll
    for (int k8 = 0; k8 < 2; k8++){
      const int ko = k8*8 + kq;
      uint32_t a[2][4], bf[8][2];
      #pragma unroll
      for (int fm=0; fm<2; fm++){
        int r = wm + fm*16 + g;
        a[fm][0] = Ab[r*20 + ko];
        a[fm][1] = Ab[(r+8)*20 + ko];
        a[fm][2] = Ab[r*20 + ko + 4];
        a[fm][3] = Ab[(r+8)*20 + ko + 4];
      }
      #pragma unroll
      for (int fn=0; fn<8; fn++){
        int r = wn + fn*8 + g;
        bf[fn][0] = Bb[r*20 + ko];
        bf[fn][1] = Bb[r*20 + ko + 4];
      }
      #pragma unroll
      for (int fm=0; fm<2; fm++)
        #pragma unroll
        for (int fn=0; fn<8; fn++)
          mma_tf32(acc[fm][fn], a[fm], bf[fn]);
    }
    if (kt+1 < nk){
      uint32_t* Aw = As[(kt+1)&1];
      uint32_t* Bw = Bs[(kt+1)&1];
      sts_tf4(&Aw[sidx],   pa0);
      sts_tf4(&Aw[sidx+4], pa1);
      sts_tf4(&Bw[sidx],   pb0);
      sts_tf4(&Bw[sidx+4], pb1);
    }
  }

  #pragma unroll
  for (int fm=0; fm<2; fm++){
    int r0 = by*128 + wm + fm*16 + g;
    #pragma unroll
    for (int fn=0; fn<8; fn++){
      int c = bx*128 + wn + fn*8 + kq*2;
      *(float2*)&C[(size_t)r0*N + c]     = make_float2(acc[fm][fn][0], acc[fm][fn][1]);
      *(float2*)&C[(size_t)(r0+8)*N + c] = make_float2(acc[fm][fn][2], acc[fm][fn][3]);
    }
  }
}

// ---------------- RoPE (interleaved pairs, pos = l mod 16) ------------------
__global__ __launch_bounds__(256) void rope_kernel(float* __restrict__ Q, float* __restrict__ Kt)
{
  const int PAIRS = CB*CL*CNH*(CHD/2);
  int i = blockIdx.x*blockDim.x + threadIdx.x;
  if (i >= 2*PAIRS) return;
  float* T = (i < PAIRS) ? Q : Kt;
  int j = (i < PAIRS) ? i : (i - PAIRS);
  int p = j & 31; j >>= 5;
  int h = j & 15; j >>= 4;
  int l = j & 2047;
  int b = j >> 11;
  float pos = (float)(l & 15);
  float ang = pos * exp2f(-(float)p * (13.287712379549449f/32.0f));
  float sn, cs;
  sincosf(ang, &sn, &cs);
  size_t base = ((size_t)(b*CL + l))*CC + h*CHD + 2*p;
  float2 x = *(float2*)&T[base];
  float2 y;
  y.x = x.x*cs - x.y*sn;
  y.y = x.y*cs + x.x*sn;
  *(float2*)&T[base] = y;
}

// ---------------- ttt_lr sigmoid dots: lr[b,h,l] ----------------------------
__global__ __launch_bounds__(256) void lr_kernel(
    const float* __restrict__ hs, const float* __restrict__ w,
    const float* __restrict__ bias, float* __restrict__ lr)
{
  __shared__ float row[CC];
  int bl = blockIdx.x;
  int tid = threadIdx.x;
  ((float4*)row)[tid] = ((const float4*)(hs + (size_t)bl*CC))[tid];
  __syncthreads();
  int h = tid >> 4, ln = tid & 15;
  float acc = 0.f;
  for (int c0 = ln*4; c0 < CC; c0 += 64){
    float4 r = *(const float4*)&row[c0];
    float4 wv = *(const float4*)&w[h*CC + c0];
    acc += r.x*wv.x + r.y*wv.y + r.z*wv.z + r.w*wv.w;
  }
  #pragma unroll
  for (int o=8;o;o>>=1) acc += __shfl_xor_sync(0xffffffffu, acc, o);
  if (ln == 0){
    int b = bl >> 11, l = bl & 2047;
    float v = acc + bias[h];
    lr[((size_t)(b*CNH + h))*CL + l] = 1.0f/(1.0f + expf(-v));
  }
}

// ---------------- scan kernel: one CTA per (b,h), split-bf16 mma ------------
// W1T[c][d]: stride 68  (W1T[c*68+d] = W1[d][c])
// W2T[d][f]: stride 260 (W2T[d*260+f] = W2[f][d])
#define OW1T 0        /* 256*68 = 17408 */
#define OW2T 17408    /* 64*260 = 16640 */
#define OB1  34048    /* 256 */
#define OB2  34304    /* 64  */
#define OLW  34368    /* 64  */
#define OLB  34432    /* 64  */
#define OXQ  34496    /* 16*68 */
#define OXK  35584
#define OXV  36672
#define OZ2  37760    /* 16*68 */
#define OG2  38848    /* 16*68 */
#define OCC  39936    /* 16*18 (NEGATED tril coeffs, stride 18 for 8B align) */
#define OTK  40224    /* 16 */
#define OLR  40240    /* 16 */
#define OCG  40256    /* 16 update coeffs */
#define OZ1  40272    /* 16*260 Z1 then X2bar */
#define OX2  44432    /* 16*260 */
#define OG1  48592    /* 16*260 */
#define SCAN_FLOATS 52752
#define SCAN_SMEM (SCAN_FLOATS*4)

__global__ __launch_bounds__(256) void scan_kernel(
  const float* __restrict__ Q, const float* __restrict__ Kx, const float* __restrict__ V,
  const float* __restrict__ LR, const float* __restrict__ lti,
  const float* __restrict__ lnw, const float* __restrict__ lnb,
  const float* __restrict__ W1g, const float* __restrict__ b1g,
  const float* __restrict__ W2g, const float* __restrict__ b2g,
  float* __restrict__ Y)
{
  extern __shared__ float sm[];
  const int t = threadIdx.x;
  const int bh = blockIdx.x;
  const int b = bh >> 4, h = bh & 15;
  float* sW1T = sm + OW1T;
  float* sW2T = sm + OW2T;
  float* sb1 = sm + OB1;
  float* sb2 = sm + OB2;
  float* sLW = sm + OLW;
  float* sLB = sm + OLB;
  float* sXQ = sm + OXQ;
  float* sXK = sm + OXK;
  float* sXV = sm + OXV;
  float* sZ2 = sm + OZ2;
  float* sG2 = sm + OG2;
  float* sC  = sm + OCC;
  float* sTok= sm + OTK;
  float* sLr = sm + OLR;
  float* sCg = sm + OCG;
  float* sZ1 = sm + OZ1;
  float* sX2 = sm + OX2;
  float* sG1 = sm + OG1;

  // init state (transposed layouts)
  for (int idx = t; idx < 16384; idx += 256) {
    int d = idx >> 8, c = idx & 255;            // W1[d][c]
    sW1T[c*68+d] = W1g[h*16384 + idx];
  }
  for (int idx = t; idx < 16384; idx += 256) {
    int f = idx >> 6, d = idx & 63;             // W2[f][d]
    sW2T[d*260+f] = W2g[h*16384 + idx];
  }
  sb1[t] = b1g[h*256+t];
  if (t < 64) { sb2[t] = b2g[h*64+t]; sLW[t] = lnw[h*64+t]; sLB[t] = lnb[h*64+t]; }
  if (t < 16) sTok[t] = fmaxf(1.0f/(float)(t+1) + lti[t], 0.0f);
  __syncthreads();

  const int i16 = t >> 4, l16 = t & 15;   // 16x16 scalar mappings
  const int wid = t >> 5;
  const int lane = t & 31;
  const int g  = lane >> 2;
  const int kq = lane & 3;
  const int nw32 = wid*32;   // warp n-slice for N=256
  const int nw8  = wid*8;    // warp n-slice for N=64

  for (int n = 0; n < CNC; n++) {
    const int l0 = n*16;
    // ===== stage 1: load tiles =====
    {
      size_t gbase = ((size_t)(b*CL + l0 + i16))*CC + h*CHD + l16*4;
      int sbase = i16*68 + l16*4;
      *(float4*)&sXQ[sbase] = *(const float4*)&Q [gbase];
      *(float4*)&sXK[sbase] = *(const float4*)&Kx[gbase];
      *(float4*)&sXV[sbase] = *(const float4*)&V [gbase];
    }
    if (t < 16) {
      float lrv = LR[((size_t)bh)*CL + l0 + t] * (1.0f/64.0f);
      sLr[t] = lrv;
      sCg[t] = sTok[15] * lrv;
    }
    __syncthreads();

    // ===== stage 2: Z1 = XK@W1 + b1 (bf16 mma) -> sZ1, sX2 ; Attn1 -> sC ===
    {
      float acc[4][4];
      #pragma unroll
      for (int a_=0;a_<4;a_++){ acc[a_][0]=0.f;acc[a_][1]=0.f;acc[a_][2]=0.f;acc[a_][3]=0.f; }
      #pragma unroll
      for (int k0=0;k0<64;k0+=16){
        FragAb af = lda_b(sXK, 0, k0, 68, 1, g, kq);
        #pragma unroll
        for (int ntl=0;ntl<4;ntl++){
          FragBb bf = ldb_b(sW1T, k0, nw32+ntl*8, 1, 68, g, kq);
          mma3b(acc[ntl], af, bf);
        }
      }
      #pragma unroll
      for (int ntl=0;ntl<4;ntl++){
        int c0 = nw32+ntl*8 + kq*2;
        float bb0 = sb1[c0], bb1 = sb1[c0+1];
        float z;
        z = acc[ntl][0]+bb0; sZ1[g*260+c0]       = z; sX2[g*260+c0]       = gelu_f(z);
        z = acc[ntl][1]+bb1; sZ1[g*260+c0+1]     = z; sX2[g*260+c0+1]     = gelu_f(z);
        z = acc[ntl][2]+bb0; sZ1[(g+8)*260+c0]   = z; sX2[(g+8)*260+c0]   = gelu_f(z);
        z = acc[ntl][3]+bb1; sZ1[(g+8)*260+c0+1] = z; sX2[(g+8)*260+c0+1] = gelu_f(z);
      }
    }
    { // Attn1 coefficients, NEGATED: sC[i][j] = -tok_i*lr_j*(xq_i.xk_j + 1), j<=i
      float c = 0.0f;
      if (l16 <= i16) {
        u64t acc = 0ULL;
        #pragma unroll
        for (int d0=0; d0<64; d0+=4) {
          float4 xq = *(const float4*)&sXQ[i16*68+d0];
          float4 xk = *(const float4*)&sXK[l16*68+d0];
          acc = f2fma(pk2(xq.x,xq.y), pk2(xk.x,xk.y), acc);
          acc = f2fma(pk2(xq.z,xq.w), pk2(xk.z,xk.w), acc);
        }
        float2 p = upk(acc);
        c = -sTok[i16]*sLr[l16]*(p.x + p.y + 1.0f);
      }
      sC[i16*18+l16] = c;
    }
    __syncthreads();

    // ===== stage 3: Z2 = X2@W2 + b2 (bf16 mma) -> sZ2 =====
    {
      float acc[4] = {0.f,0.f,0.f,0.f};
      #pragma unroll 8
      for (int k0=0;k0<256;k0+=16){
        FragAb af = lda_b(sX2, 0, k0, 260, 1, g, kq);
        FragBb bf = ldb_b(sW2T, k0, nw8, 1, 260, g, kq);
        mma3b(acc, af, bf);
      }
      int c0 = nw8 + kq*2;
      sZ2[g*68+c0]       = acc[0] + sb2[c0];
      sZ2[g*68+c0+1]     = acc[1] + sb2[c0+1];
      sZ2[(g+8)*68+c0]   = acc[2] + sb2[c0];
      sZ2[(g+8)*68+c0+1] = acc[3] + sb2[c0+1];
    }
    __syncthreads();

    // ===== stage 4: gZ2 = ln_fused_l2_bwd(Z2, XV-XK) (scalar) =====
    {
      int base = i16*68 + l16*4;
      float4 x = *(const float4*)&sZ2[base];
      float s  = x.x+x.y+x.z+x.w;
      float ss = x.x*x.x + x.y*x.y + x.z*x.z + x.w*x.w;
      #pragma unroll
      for (int o=8;o;o>>=1){ s += __shfl_xor_sync(0xffffffffu, s, o); ss += __shfl_xor_sync(0xffffffffu, ss, o); }
      float mu = s*(1.0f/64.0f);
      float var = ss*(1.0f/64.0f) - mu*mu;
      float rstd = rsqrtf(var + 1e-6f);
      float4 xh;
      xh.x=(x.x-mu)*rstd; xh.y=(x.y-mu)*rstd; xh.z=(x.z-mu)*rstd; xh.w=(x.w-mu)*rstd;
      float4 gw = *(const float4*)&sLW[l16*4];
      float4 bb = *(const float4*)&sLB[l16*4];
      float4 xv = *(const float4*)&sXV[base];
      float4 xk = *(const float4*)&sXK[base];
      float4 go;
      go.x = (gw.x*xh.x + bb.x - (xv.x - xk.x))*gw.x;
      go.y = (gw.y*xh.y + bb.y - (xv.y - xk.y))*gw.y;
      go.z = (gw.z*xh.z + bb.z - (xv.z - xk.z))*gw.z;
      go.w = (gw.w*xh.w + bb.w - (xv.w - xk.w))*gw.w;
      float sg  = go.x+go.y+go.z+go.w;
      float sgx = go.x*xh.x + go.y*xh.y + go.z*xh.z + go.w*xh.w;
      #pragma unroll
      for (int o=8;o;o>>=1){ sg += __shfl_xor_sync(0xffffffffu, sg, o); sgx += __shfl_xor_sync(0xffffffffu, sgx, o); }
      float k1 = rstd*(1.0f/64.0f);
      float4 o4;
      o4.x = (64.0f*go.x - sg - xh.x*sgx)*k1;
      o4.y = (64.0f*go.y - sg - xh.y*sgx)*k1;
      o4.z = (64.0f*go.z - sg - xh.z*sgx)*k1;
      o4.w = (64.0f*go.w - sg - xh.w*sgx)*k1;
      *(float4*)&sG2[base] = o4;
    }
    __syncthreads();

    // ===== stage 5: gZ1 = (gZ2 @ W2^T) * gelu'(Z1) (bf16 mma) -> sG1 =====
    {
      float acc[4][4];
      #pragma unroll
      for (int a_=0;a_<4;a_++){ acc[a_][0]=0.f;acc[a_][1]=0.f;acc[a_][2]=0.f;acc[a_][3]=0.f; }
      #pragma unroll
      for (int k0=0;k0<64;k0+=16){
        FragAb af = lda_b(sG2, 0, k0, 68, 1, g, kq);
        #pragma unroll
        for (int ntl=0;ntl<4;ntl++){
          FragBb bf = ldb_b(sW2T, k0, nw32+ntl*8, 260, 1, g, kq);
          mma3b(acc[ntl], af, bf);
        }
      }
      #pragma unroll
      for (int ntl=0;ntl<4;ntl++){
        int c0 = nw32+ntl*8 + kq*2;
        sG1[g*260+c0]       = acc[ntl][0]*gelu_bwd_f(sZ1[g*260+c0]);
        sG1[g*260+c0+1]     = acc[ntl][1]*gelu_bwd_f(sZ1[g*260+c0+1]);
        sG1[(g+8)*260+c0]   = acc[ntl][2]*gelu_bwd_f(sZ1[(g+8)*260+c0]);
        sG1[(g+8)*260+c0+1] = acc[ntl][3]*gelu_bwd_f(sZ1[(g+8)*260+c0+1]);
      }
    }
    __syncthreads();

    // ===== stage 6: Z1bar = XQ@W1 + (-C)@gZ1 + b1 ; X2bar = gelu -> sZ1 ====
    {
      float acc[4][4];
      #pragma unroll
      for (int a_=0;a_<4;a_++){ acc[a_][0]=0.f;acc[a_][1]=0.f;acc[a_][2]=0.f;acc[a_][3]=0.f; }
      #pragma unroll
      for (int k0=0;k0<64;k0+=16){
        FragAb af = lda_b(sXQ, 0, k0, 68, 1, g, kq);
        #pragma unroll
        for (int ntl=0;ntl<4;ntl++){
          FragBb bf = ldb_b(sW1T, k0, nw32+ntl*8, 1, 68, g, kq);
          mma3b(acc[ntl], af, bf);
        }
      }
      {
        FragAb af = lda_b(sC, 0, 0, 18, 1, g, kq);
        #pragma unroll
        for (int ntl=0;ntl<4;ntl++){
          FragBb bf = ldb_b(sG1, 0, nw32+ntl*8, 260, 1, g, kq);
          mma3b(acc[ntl], af, bf);
        }
      }
      #pragma unroll
      for (int ntl=0;ntl<4;ntl++){
        int c0 = nw32+ntl*8 + kq*2;
        float bb0 = sb1[c0], bb1 = sb1[c0+1];
        sZ1[g*260+c0]       = gelu_f(acc[ntl][0]+bb0);
        sZ1[g*260+c0+1]     = gelu_f(acc[ntl][1]+bb1);
        sZ1[(g+8)*260+c0]   = gelu_f(acc[ntl][2]+bb0);
        sZ1[(g+8)*260+c0+1] = gelu_f(acc[ntl][3]+bb1);
      }
    }
    __syncthreads();

    // ===== stage 7: Attn2 coeffs (NEGATED) -> sC =====
    {
      float c = 0.0f;
      if (l16 <= i16) {
        u64t acc = 0ULL;
        #pragma unroll 8
        for (int f0=0; f0<256; f0+=4) {
          float4 xb = *(const float4*)&sZ1[i16*260+f0];
          float4 x2 = *(const float4*)&sX2[l16*260+f0];
          acc = f2fma(pk2(xb.x,xb.y), pk2(x2.x,x2.y), acc);
          acc = f2fma(pk2(xb.z,xb.w), pk2(x2.z,x2.w), acc);
        }
        float2 p = upk(acc);
        c = -sTok[i16]*sLr[l16]*(p.x + p.y + 1.0f);
      }
      sC[i16*18+l16] = c;
    }
    __syncthreads();

    // ===== stage 8: Z2bar = X2bar@W2 + (-C)@gZ2 + b2 (bf16 mma) -> sZ2 =====
    {
      float acc[4] = {0.f,0.f,0.f,0.f};
      #pragma unroll 8
      for (int k0=0;k0<256;k0+=16){
        FragAb af = lda_b(sZ1, 0, k0, 260, 1, g, kq);
        FragBb bf = ldb_b(sW2T, k0, nw8, 1, 260, g, kq);
        mma3b(acc, af, bf);
      }
      {
        FragAb af = lda_b(sC, 0, 0, 18, 1, g, kq);
        FragBb bf = ldb_b(sG2, 0, nw8, 68, 1, g, kq);
        mma3b(acc, af, bf);
      }
      int c0 = nw8 + kq*2;
      sZ2[g*68+c0]       = acc[0] + sb2[c0];
      sZ2[g*68+c0+1]     = acc[1] + sb2[c0+1];
      sZ2[(g+8)*68+c0]   = acc[2] + sb2[c0];
      sZ2[(g+8)*68+c0+1] = acc[3] + sb2[c0+1];
    }
    __syncthreads();

    // ===== stage 9: output + state updates =====
    { // Y = XQ + ln_fwd(Z2bar)
      int base = i16*68 + l16*4;
      float4 x = *(const float4*)&sZ2[base];
      float s  = x.x+x.y+x.z+x.w;
      float ss = x.x*x.x + x.y*x.y + x.z*x.z + x.w*x.w;
      #pragma unroll
      for (int o=8;o;o>>=1){ s += __shfl_xor_sync(0xffffffffu, s, o); ss += __shfl_xor_sync(0xffffffffu, ss, o); }
      float mu = s*(1.0f/64.0f);
      float var = ss*(1.0f/64.0f) - mu*mu;
      float rstd = rsqrtf(var + 1e-6f);
      float4 gw = *(const float4*)&sLW[l16*4];
      float4 bb = *(const float4*)&sLB[l16*4];
      float4 xq = *(const float4*)&sXQ[base];
      float4 o4;
      o4.x = gw.x*(x.x-mu)*rstd + bb.x + xq.x;
      o4.y = gw.y*(x.y-mu)*rstd + bb.y + xq.y;
      o4.z = gw.z*(x.z-mu)*rstd + bb.z + xq.z;
      o4.w = gw.w*(x.w-mu)*rstd + bb.w + xq.w;
      size_t gbase = ((size_t)(b*CL + l0 + i16))*CC + h*CHD + l16*4;
      *(float4*)&Y[gbase] = o4;
    }
    // W1T[c][d] -= sum_j XK[j][d] * (cg_j * gZ1[j][c])   (bf16 mma, m=d tiles)
    {
      #pragma unroll
      for (int mt=0; mt<4; mt++){
        float acc[4][4];
        #pragma unroll
        for (int a_=0;a_<4;a_++){ acc[a_][0]=0.f;acc[a_][1]=0.f;acc[a_][2]=0.f;acc[a_][3]=0.f; }
        FragAb af = lda_b(sXK, mt*16, 0, 1, 68, g, kq);
        #pragma unroll
        for (int ntl=0;ntl<4;ntl++){
          FragBb bf = ldb_bs(sG1, 0, nw32+ntl*8, 260, 1, g, kq, sCg);
          mma3b(acc[ntl], af, bf);
        }
        int d0 = mt*16 + g;
        #pragma unroll
        for (int ntl=0;ntl<4;ntl++){
          int c0 = nw32+ntl*8 + kq*2;
          sW1T[c0*68+d0]       -= acc[ntl][0];
          sW1T[(c0+1)*68+d0]   -= acc[ntl][1];
          sW1T[c0*68+d0+8]     -= acc[ntl][2];
          sW1T[(c0+1)*68+d0+8] -= acc[ntl][3];
        }
      }
    }
    // W2T[d][f] -= sum_j (cg_j * gZ2[j][d]) * X2[j][f]   (bf16 mma, m=d tiles)
    {
      #pragma unroll
      for (int mt=0; mt<4; mt++){
        float acc[4][4];
        #pragma unroll
        for (int a_=0;a_<4;a_++){ acc[a_][0]=0.f;acc[a_][1]=0.f;acc[a_][2]=0.f;acc[a_][3]=0.f; }
        FragAb af = lda_bs(sG2, mt*16, 0, 1, 68, g, kq, sCg);
        #pragma unroll
        for (int ntl=0;ntl<4;ntl++){
          FragBb bf = ldb_b(sX2, 0, nw32+ntl*8, 260, 1, g, kq);
          mma3b(acc[ntl], af, bf);
        }
        int d0 = mt*16 + g;
        #pragma unroll
        for (int ntl=0;ntl<4;ntl++){
          int f0 = nw32+ntl*8 + kq*2;
          sW2T[d0*260+f0]       -= acc[ntl][0];
          sW2T[d0*260+f0+1]     -= acc[ntl][1];
          sW2T[(d0+8)*260+f0]   -= acc[ntl][2];
          sW2T[(d0+8)*260+f0+1] -= acc[ntl][3];
        }
      }
    }
    // bias updates (scalar)
    {
      float s1 = 0.f;
      #pragma unroll
      for (int j=0;j<16;j++) s1 += sCg[j]*sG1[j*260+t];
      sb1[t] -= s1;
      if (t < 64){
        float s2 = 0.f;
        #pragma unroll
        for (int j=0;j<16;j++) s2 += sCg[j]*sG2[j*68+t];
        sb2[t] -= s2;
      }
    }
    __syncthreads();
  }
}

// ---------------- post layernorm over C=1024 --------------------------------
__global__ __launch_bounds__(256) void postln_kernel(
    const float* __restrict__ X, const float* __restrict__ g,
    const float* __restrict__ b, float* __restrict__ O)
{
  __shared__ float rs[8], rss[8], stats[2];
  int row = blockIdx.x, t = threadIdx.x;
  float4 x = ((const float4*)(X + (size_t)row*CC))[t];
  float s  = x.x+x.y+x.z+x.w;
  float ss = x.x*x.x + x.y*x.y + x.z*x.z + x.w*x.w;
  #pragma unroll
  for (int o=16;o;o>>=1){ s += __shfl_xor_sync(0xffffffffu, s, o); ss += __shfl_xor_sync(0xffffffffu, ss, o); }
  if ((t & 31) == 0){ rs[t>>5] = s; rss[t>>5] = ss; }
  __syncthreads();
  if (t == 0){
    float a=0.f, c=0.f;
    #pragma unroll
    for (int w=0;w<8;w++){ a += rs[w]; c += rss[w]; }
    stats[0] = a*(1.0f/1024.0f);
    stats[1] = c*(1.0f/1024.0f);
  }
  __syncthreads();
  float mu = stats[0];
  float var = stats[1] - mu*mu;
  float rstd = rsqrtf(var + 1e-6f);
  float4 gv = ((const float4*)g)[t];
  float4 bv = ((const float4*)b)[t];
  float4 o4;
  o4.x = gv.x*(x.x-mu)*rstd + bv.x;
  o4.y = gv.y*(x.y-mu)*rstd + bv.y;
  o4.z = gv.z*(x.z-mu)*rstd + bv.z;
  o4.w = gv.w*(x.w-mu)*rstd + bv.w;
  ((float4*)(O + (size_t)row*CC))[t] = o4;
}

// ---------------- launch -----------------------------------------------------
extern "C" void kernel_launch(void* const* d_in, const int* in_sizes, int n_in,
                              void* d_out, int out_size)
{
  const float* hs  = (const float*)d_in[0];
  const float* wq  = (const float*)d_in[1];
  const float* wk  = (const float*)d_in[2];
  const float* wv  = (const float*)d_in[3];
  const float* wo  = (const float*)d_in[4];
  const float* lti = (const float*)d_in[5];
  const float* lrw = (const float*)d_in[6];
  const float* lrb = (const float*)d_in[7];
  const float* tnw = (const float*)d_in[8];
  const float* tnb = (const float*)d_in[9];
  const float* pnw = (const float*)d_in[10];
  const float* pnb = (const float*)d_in[11];
  const float* W1  = (const float*)d_in[12];
  const float* b1  = (const float*)d_in[13];
  const float* W2  = (const float*)d_in[14];
  const float* b2  = (const float*)d_in[15];
  float* out = (float*)d_out;

  float *pQ, *pK, *pV, *pY, *pLR;
  cudaGetSymbolAddress((void**)&pQ,  g_Q);
  cudaGetSymbolAddress((void**)&pK,  g_K);
  cudaGetSymbolAddress((void**)&pV,  g_V);
  cudaGetSymbolAddress((void**)&pY,  g_Y);
  cudaGetSymbolAddress((void**)&pLR, g_LR);

  cudaFuncSetAttribute(scan_kernel, cudaFuncAttributeMaxDynamicSharedMemorySize, SCAN_SMEM);

  const int M = CB*CL;  // 8192
  const int GG = (M/128)*(CC/128);  // 512
  gemm_tf32<<<GG, 256>>>(hs, wq, pQ, M, CC, CC);
  gemm_tf32<<<GG, 256>>>(hs, wk, pK, M, CC, CC);
  gemm_tf32<<<GG, 256>>>(hs, wv, pV, M, CC, CC);
  rope_kernel<<<(2*CB*CL*CNH*(CHD/2))/256, 256>>>(pQ, pK);
  lr_kernel<<<CB*CL, 256>>>(hs, lrw, lrb, pLR);
  scan_kernel<<<CB*CNH, 256, SCAN_SMEM>>>(pQ, pK, pV, pLR, lti, tnw, tnb,
                                          W1, b1, W2, b2, pY);
  postln_kernel<<<CB*CL, 256>>>(pY, pnw, pnb, pQ);
  gemm_tf32<<<GG, 256>>>(pQ, wo, out, M, CC, CC);
}